// round 1
// baseline (speedup 1.0000x reference)
#include <cuda_runtime.h>
#include <cstdint>
#include <cstddef>

// ---------------------------------------------------------------------------
// MultiheadedAttention2: out = softmax_over_batch((q@k^T)*scale) path
//   k = key   @ Wk^T + bk        [B,T,HE]
//   q = query @ Wq^T + bq        [B,T,HE]
//   v = value @ Wv^T + bv        [B,T,HE]
//   prod[b,t,s] = sum_e q[b,t,e]*k[b,s,e] * SCALE
//   att = softmax(prod, axis=b)            (batch-axis softmax, 8 entries)
//   attended[b,t,h] = sum_s att[b,t,s]*v[b,s,h]
//   out = attended @ Wo^T + bo   [B,T,E]
// All GEMMs via tf32 mma.sync (fp32 accumulate, cvt.rna inputs).
// ---------------------------------------------------------------------------

#define B_SZ 8
#define T_SZ 2048
#define E_SZ 512
#define HE_SZ 4096
#define SCALE_F 0.04419417382415922f  // 512^-0.5

// Scratch (device globals; allocation-free rule)
__device__ float g_q[(size_t)B_SZ * T_SZ * HE_SZ];
__device__ float g_k[(size_t)B_SZ * T_SZ * HE_SZ];
__device__ float g_v[(size_t)B_SZ * T_SZ * HE_SZ];
__device__ float g_att[(size_t)B_SZ * T_SZ * T_SZ];
__device__ float g_att2[(size_t)B_SZ * T_SZ * HE_SZ];

static __device__ __forceinline__ uint32_t f2tf32(float x) {
    uint32_t u;
    asm volatile("cvt.rna.tf32.f32 %0, %1;" : "=r"(u) : "f"(x));
    return u;
}

static __device__ __forceinline__ void mma_tf32(float* c, const uint32_t* a, const uint32_t* b) {
    asm volatile(
        "mma.sync.aligned.m16n8k8.row.col.f32.tf32.tf32.f32 "
        "{%0,%1,%2,%3}, {%4,%5,%6,%7}, {%8,%9}, {%0,%1,%2,%3};\n"
        : "+f"(c[0]), "+f"(c[1]), "+f"(c[2]), "+f"(c[3])
        : "r"(a[0]), "r"(a[1]), "r"(a[2]), "r"(a[3]), "r"(b[0]), "r"(b[1]));
}

// C[M,N] = alpha * (A @ opB) (+ bias).  A row-major [M,K].
// TRANS_B: B row-major [N,K] (opB = B^T).  else: B row-major [K,N].
// M % 128 == 0, N % 128 == 0, K % 32 == 0 for all calls here.
template <bool TRANS_B, bool HAS_BIAS>
__global__ __launch_bounds__(256, 1)
void gemm_tf32(const float* __restrict__ A, const float* __restrict__ Bm,
               const float* __restrict__ bias, float* __restrict__ C,
               int M, int N, int K, float alpha,
               long long sA, long long sB, long long sC)
{
    __shared__ float smem[9216];  // 36 KB: As [128][36] + Bs ([128][36] or [32][136])
    float (*As)[36] = reinterpret_cast<float(*)[36]>(smem);
    float (*BsT)[36] = reinterpret_cast<float(*)[36]>(smem + 4608);
    float (*BsN)[136] = reinterpret_cast<float(*)[136]>(smem + 4608);

    const float* Ab = A + (long long)blockIdx.z * sA;
    const float* Bb = Bm + (long long)blockIdx.z * sB;
    float* Cb = C + (long long)blockIdx.z * sC;

    const int bm = blockIdx.y * 128;
    const int bn = blockIdx.x * 128;
    const int tid = threadIdx.x;
    const int lane = tid & 31;
    const int warp = tid >> 5;
    const int wm = (warp & 3) * 32;   // warp tile row base (4 warps down M)
    const int wn = (warp >> 2) * 64;  // warp tile col base (2 warps across N)
    const int gr = lane >> 2;         // group row (0..7)
    const int gc = lane & 3;          // thread-in-group (0..3)

    float acc[2][8][4];
#pragma unroll
    for (int i = 0; i < 2; ++i)
#pragma unroll
        for (int j = 0; j < 8; ++j)
#pragma unroll
            for (int r = 0; r < 4; ++r) acc[i][j][r] = 0.f;

    const int ldrow = tid >> 3;        // 0..31
    const int ldcol = (tid & 7) << 2;  // 0,4,...,28
    const int nrow = tid >> 5;         // 0..7   (NN B loads)
    const int ncol = (tid & 31) << 2;  // 0..124 (NN B loads)

    for (int kt = 0; kt < K; kt += 32) {
        // ---- A tile: [128][32] from A[bm..][kt..] ----
#pragma unroll
        for (int p = 0; p < 4; ++p) {
            const float4 t4 = *reinterpret_cast<const float4*>(
                Ab + (size_t)(bm + ldrow + p * 32) * K + (kt + ldcol));
            float* dst = &As[ldrow + p * 32][ldcol];
            dst[0] = __uint_as_float(f2tf32(t4.x));
            dst[1] = __uint_as_float(f2tf32(t4.y));
            dst[2] = __uint_as_float(f2tf32(t4.z));
            dst[3] = __uint_as_float(f2tf32(t4.w));
        }
        // ---- B tile ----
        if (TRANS_B) {
            // B [N,K] row-major; store as [n][k] (same layout as A)
#pragma unroll
            for (int p = 0; p < 4; ++p) {
                const float4 t4 = *reinterpret_cast<const float4*>(
                    Bb + (size_t)(bn + ldrow + p * 32) * K + (kt + ldcol));
                float* dst = &BsT[ldrow + p * 32][ldcol];
                dst[0] = __uint_as_float(f2tf32(t4.x));
                dst[1] = __uint_as_float(f2tf32(t4.y));
                dst[2] = __uint_as_float(f2tf32(t4.z));
                dst[3] = __uint_as_float(f2tf32(t4.w));
            }
        } else {
            // B [K,N] row-major; store as [k][n]
#pragma unroll
            for (int p = 0; p < 4; ++p) {
                const float4 t4 = *reinterpret_cast<const float4*>(
                    Bb + (size_t)(kt + nrow + p * 8) * N + (bn + ncol));
                float* dst = &BsN[nrow + p * 8][ncol];
                dst[0] = __uint_as_float(f2tf32(t4.x));
                dst[1] = __uint_as_float(f2tf32(t4.y));
                dst[2] = __uint_as_float(f2tf32(t4.z));
                dst[3] = __uint_as_float(f2tf32(t4.w));
            }
        }
        __syncthreads();

#pragma unroll
        for (int k0 = 0; k0 < 32; k0 += 8) {
            uint32_t a[2][4];
#pragma unroll
            for (int i = 0; i < 2; ++i) {
                const int r = wm + i * 16 + gr;
                a[i][0] = __float_as_uint(As[r][k0 + gc]);
                a[i][1] = __float_as_uint(As[r + 8][k0 + gc]);
                a[i][2] = __float_as_uint(As[r][k0 + gc + 4]);
                a[i][3] = __float_as_uint(As[r + 8][k0 + gc + 4]);
            }
            uint32_t b[8][2];
            if (TRANS_B) {
#pragma unroll
                for (int j = 0; j < 8; ++j) {
                    const int cn = wn + j * 8 + gr;
                    b[j][0] = __float_as_uint(BsT[cn][k0 + gc]);
                    b[j][1] = __float_as_uint(BsT[cn][k0 + gc + 4]);
                }
            } else {
#pragma unroll
                for (int j = 0; j < 8; ++j) {
                    const int cn = wn + j * 8 + gr;
                    b[j][0] = __float_as_uint(BsN[k0 + gc][cn]);
                    b[j][1] = __float_as_uint(BsN[k0 + gc + 4][cn]);
                }
            }
#pragma unroll
            for (int i = 0; i < 2; ++i)
#pragma unroll
                for (int j = 0; j < 8; ++j) mma_tf32(acc[i][j], a[i], b[j]);
        }
        __syncthreads();
    }

    // ---- epilogue ----
#pragma unroll
    for (int i = 0; i < 2; ++i) {
#pragma unroll
        for (int j = 0; j < 8; ++j) {
            const int row = bm + wm + i * 16 + gr;
            const int col = bn + wn + j * 8 + gc * 2;
            float v0 = acc[i][j][0] * alpha;
            float v1 = acc[i][j][1] * alpha;
            float v2 = acc[i][j][2] * alpha;
            float v3 = acc[i][j][3] * alpha;
            if (HAS_BIAS) {
                const float b0 = bias[col], b1 = bias[col + 1];
                v0 += b0; v1 += b1; v2 += b0; v3 += b1;
            }
            Cb[(size_t)row * N + col] = v0;
            Cb[(size_t)row * N + col + 1] = v1;
            Cb[(size_t)(row + 8) * N + col] = v2;
            Cb[(size_t)(row + 8) * N + col + 1] = v3;
        }
    }
}

// Softmax across the batch axis: for each (t,s) flat index i, normalize the 8
// values at d[b*plane + i].
__global__ void softmax_b8(float* __restrict__ d, int plane)
{
    const int i = blockIdx.x * blockDim.x + threadIdx.x;
    if (i >= plane) return;
    float v[B_SZ];
    float m = -1e30f;
#pragma unroll
    for (int b = 0; b < B_SZ; ++b) {
        v[b] = d[(size_t)b * plane + i];
        m = fmaxf(m, v[b]);
    }
    float s = 0.f;
#pragma unroll
    for (int b = 0; b < B_SZ; ++b) {
        v[b] = __expf(v[b] - m);
        s += v[b];
    }
    const float inv = 1.f / s;
#pragma unroll
    for (int b = 0; b < B_SZ; ++b) d[(size_t)b * plane + i] = v[b] * inv;
}

extern "C" void kernel_launch(void* const* d_in, const int* in_sizes, int n_in,
                              void* d_out, int out_size)
{
    (void)in_sizes; (void)n_in; (void)out_size;
    const float* key   = (const float*)d_in[0];
    const float* value = (const float*)d_in[1];
    const float* query = (const float*)d_in[2];
    const float* Wk = (const float*)d_in[3];
    const float* bk = (const float*)d_in[4];
    const float* Wv = (const float*)d_in[5];
    const float* bv = (const float*)d_in[6];
    const float* Wq = (const float*)d_in[7];
    const float* bq = (const float*)d_in[8];
    const float* Wo = (const float*)d_in[9];
    const float* bo = (const float*)d_in[10];
    float* out = (float*)d_out;

    float *q, *k, *v, *att, *att2;
    cudaGetSymbolAddress((void**)&q, g_q);
    cudaGetSymbolAddress((void**)&k, g_k);
    cudaGetSymbolAddress((void**)&v, g_v);
    cudaGetSymbolAddress((void**)&att, g_att);
    cudaGetSymbolAddress((void**)&att2, g_att2);

    const int MT = B_SZ * T_SZ;  // 16384
    const dim3 blk(256);

    // projections: [16384,512] @ [4096,512]^T + bias
    {
        dim3 grid(HE_SZ / 128, MT / 128, 1);
        gemm_tf32<true, true><<<grid, blk>>>(key, Wk, bk, k, MT, HE_SZ, E_SZ, 1.f, 0, 0, 0);
        gemm_tf32<true, true><<<grid, blk>>>(query, Wq, bq, q, MT, HE_SZ, E_SZ, 1.f, 0, 0, 0);
        gemm_tf32<true, true><<<grid, blk>>>(value, Wv, bv, v, MT, HE_SZ, E_SZ, 1.f, 0, 0, 0);
    }
    // logits: per batch, [2048,4096] @ [2048,4096]^T * SCALE
    {
        dim3 grid(T_SZ / 128, T_SZ / 128, B_SZ);
        const long long sqk = (long long)T_SZ * HE_SZ;
        const long long sp = (long long)T_SZ * T_SZ;
        gemm_tf32<true, false><<<grid, blk>>>(q, k, nullptr, att, T_SZ, T_SZ, HE_SZ,
                                              SCALE_F, sqk, sqk, sp);
    }
    // batch-axis softmax over 8 values
    {
        const int plane = T_SZ * T_SZ;
        softmax_b8<<<plane / 256, 256>>>(att, plane);
    }
    // attend: per batch, [2048,2048] @ [2048,4096]
    {
        dim3 grid(HE_SZ / 128, T_SZ / 128, B_SZ);
        const long long sp = (long long)T_SZ * T_SZ;
        const long long sv = (long long)T_SZ * HE_SZ;
        gemm_tf32<false, false><<<grid, blk>>>(att, v, nullptr, att2, T_SZ, HE_SZ, T_SZ,
                                               1.f, sp, sv, sv);
    }
    // output projection: [16384,4096] @ [512,4096]^T + bias
    {
        dim3 grid(E_SZ / 128, MT / 128, 1);
        gemm_tf32<true, true><<<grid, blk>>>(att2, Wo, bo, out, MT, E_SZ, HE_SZ, 1.f, 0, 0, 0);
    }
}

// round 2
// speedup vs baseline: 1.2130x; 1.2130x over previous
#include <cuda_runtime.h>
#include <cstdint>
#include <cstddef>

// ---------------------------------------------------------------------------
// MultiheadedAttention2 (batch-axis softmax quirk), tf32 mma.sync pipeline v2:
//   4-stage cp.async double buffering, cvt.rna at fragment load, 1 barrier/tile.
// ---------------------------------------------------------------------------

#define B_SZ 8
#define T_SZ 2048
#define E_SZ 512
#define HE_SZ 4096
#define SCALE_F 0.04419417382415922f  // 512^-0.5

#define STAGES 4
#define STAGE_FLOATS 9216          // A: 128*36  +  B: 128*36 (or 32*136)
#define SMEM_BYTES (STAGES * STAGE_FLOATS * 4)  // 147456

// Scratch (device globals; allocation-free rule)
__device__ float g_q[(size_t)B_SZ * T_SZ * HE_SZ];
__device__ float g_k[(size_t)B_SZ * T_SZ * HE_SZ];
__device__ float g_v[(size_t)B_SZ * T_SZ * HE_SZ];
__device__ float g_att[(size_t)B_SZ * T_SZ * T_SZ];
__device__ float g_att2[(size_t)B_SZ * T_SZ * HE_SZ];

static __device__ __forceinline__ uint32_t f2tf32(float x) {
    uint32_t u;
    asm volatile("cvt.rna.tf32.f32 %0, %1;" : "=r"(u) : "f"(x));
    return u;
}

static __device__ __forceinline__ void mma_tf32(float* c, const uint32_t* a, const uint32_t* b) {
    asm volatile(
        "mma.sync.aligned.m16n8k8.row.col.f32.tf32.tf32.f32 "
        "{%0,%1,%2,%3}, {%4,%5,%6,%7}, {%8,%9}, {%0,%1,%2,%3};\n"
        : "+f"(c[0]), "+f"(c[1]), "+f"(c[2]), "+f"(c[3])
        : "r"(a[0]), "r"(a[1]), "r"(a[2]), "r"(a[3]), "r"(b[0]), "r"(b[1]));
}

static __device__ __forceinline__ void cp_async16(float* smem_dst, const float* gptr) {
    uint32_t s = (uint32_t)__cvta_generic_to_shared(smem_dst);
    asm volatile("cp.async.cg.shared.global [%0], [%1], 16;\n" :: "r"(s), "l"(gptr));
}
static __device__ __forceinline__ void cp_commit() {
    asm volatile("cp.async.commit_group;\n");
}
template <int N>
static __device__ __forceinline__ void cp_wait() {
    asm volatile("cp.async.wait_group %0;\n" :: "n"(N));
}

// C[M,N] = alpha * (A @ opB) (+ bias).  A row-major [M,K].
// TRANS_B: B row-major [N,K] (opB = B^T).  else: B row-major [K,N].
// M % 128 == 0, N % 128 == 0, K % 32 == 0 for all calls here.
template <bool TRANS_B, bool HAS_BIAS>
__global__ __launch_bounds__(256, 1)
void gemm_tf32(const float* __restrict__ A, const float* __restrict__ Bm,
               const float* __restrict__ bias, float* __restrict__ C,
               int M, int N, int K, float alpha,
               long long sA, long long sB, long long sC)
{
    extern __shared__ float smem[];  // STAGES * (A[128][36] + B[128][36]/[32][136])

    const float* Ab = A + (long long)blockIdx.z * sA;
    const float* Bb = Bm + (long long)blockIdx.z * sB;
    float* Cb = C + (long long)blockIdx.z * sC;

    const int bm = blockIdx.y * 128;
    const int bn = blockIdx.x * 128;
    const int tid = threadIdx.x;
    const int lane = tid & 31;
    const int warp = tid >> 5;
    const int wm = (warp & 3) * 32;   // warp tile row base (4 warps down M)
    const int wn = (warp >> 2) * 64;  // warp tile col base (2 warps across N)
    const int gr = lane >> 2;         // group row (0..7)
    const int gc = lane & 3;          // thread-in-group (0..3)

    float acc[2][8][4];
#pragma unroll
    for (int i = 0; i < 2; ++i)
#pragma unroll
        for (int j = 0; j < 8; ++j)
#pragma unroll
            for (int r = 0; r < 4; ++r) acc[i][j][r] = 0.f;

    const int ldrow = tid >> 3;        // 0..31
    const int ldcol = (tid & 7) << 2;  // 0,4,...,28
    const int nrow = tid >> 5;         // 0..7   (NN B loads)
    const int ncol = (tid & 31) << 2;  // 0..124 (NN B loads)

    const int nk = K >> 5;

    // Issue all cp.async for one k-tile into the given stage.
    auto load_tile = [&](int kt, int stage) {
        float* sA = smem + stage * STAGE_FLOATS;
        float* sB = sA + 4608;
        const int k0g = kt << 5;
#pragma unroll
        for (int p = 0; p < 4; ++p) {
            const int r = ldrow + p * 32;
            cp_async16(sA + r * 36 + ldcol, Ab + (size_t)(bm + r) * K + (k0g + ldcol));
        }
        if (TRANS_B) {
#pragma unroll
            for (int p = 0; p < 4; ++p) {
                const int r = ldrow + p * 32;
                cp_async16(sB + r * 36 + ldcol, Bb + (size_t)(bn + r) * K + (k0g + ldcol));
            }
        } else {
#pragma unroll
            for (int p = 0; p < 4; ++p) {
                const int r = nrow + p * 8;  // k within tile
                cp_async16(sB + r * 136 + ncol, Bb + (size_t)(k0g + r) * N + (bn + ncol));
            }
        }
    };

    // Prologue: prefetch STAGES-1 tiles.
#pragma unroll
    for (int s = 0; s < STAGES - 1; ++s) {
        if (s < nk) load_tile(s, s);
        cp_commit();
    }

    for (int kt = 0; kt < nk; ++kt) {
        const int stage = kt & (STAGES - 1);
        cp_wait<STAGES - 2>();
        __syncthreads();

        const int pf = kt + STAGES - 1;
        if (pf < nk) load_tile(pf, pf & (STAGES - 1));
        cp_commit();

        const float* sA = smem + stage * STAGE_FLOATS;
        const float* sB = sA + 4608;

#pragma unroll
        for (int k0 = 0; k0 < 32; k0 += 8) {
            uint32_t a[2][4];
#pragma unroll
            for (int i = 0; i < 2; ++i) {
                const int r = wm + i * 16 + gr;
                a[i][0] = f2tf32(sA[(size_t)r * 36 + k0 + gc]);
                a[i][1] = f2tf32(sA[(size_t)(r + 8) * 36 + k0 + gc]);
                a[i][2] = f2tf32(sA[(size_t)r * 36 + k0 + gc + 4]);
                a[i][3] = f2tf32(sA[(size_t)(r + 8) * 36 + k0 + gc + 4]);
            }
            uint32_t b[8][2];
            if (TRANS_B) {
#pragma unroll
                for (int j = 0; j < 8; ++j) {
                    const int cn = wn + j * 8 + gr;
                    b[j][0] = f2tf32(sB[(size_t)cn * 36 + k0 + gc]);
                    b[j][1] = f2tf32(sB[(size_t)cn * 36 + k0 + gc + 4]);
                }
            } else {
#pragma unroll
                for (int j = 0; j < 8; ++j) {
                    const int cn = wn + j * 8 + gr;
                    b[j][0] = f2tf32(sB[(size_t)(k0 + gc) * 136 + cn]);
                    b[j][1] = f2tf32(sB[(size_t)(k0 + gc + 4) * 136 + cn]);
                }
            }
#pragma unroll
            for (int i = 0; i < 2; ++i)
#pragma unroll
                for (int j = 0; j < 8; ++j) mma_tf32(acc[i][j], a[i], b[j]);
        }
        __syncthreads();
    }

    // ---- epilogue ----
#pragma unroll
    for (int i = 0; i < 2; ++i) {
#pragma unroll
        for (int j = 0; j < 8; ++j) {
            const int row = bm + wm + i * 16 + gr;
            const int col = bn + wn + j * 8 + gc * 2;
            float v0 = acc[i][j][0] * alpha;
            float v1 = acc[i][j][1] * alpha;
            float v2 = acc[i][j][2] * alpha;
            float v3 = acc[i][j][3] * alpha;
            if (HAS_BIAS) {
                const float b0 = bias[col], b1 = bias[col + 1];
                v0 += b0; v1 += b1; v2 += b0; v3 += b1;
            }
            Cb[(size_t)row * N + col] = v0;
            Cb[(size_t)row * N + col + 1] = v1;
            Cb[(size_t)(row + 8) * N + col] = v2;
            Cb[(size_t)(row + 8) * N + col + 1] = v3;
        }
    }
}

// Softmax across the batch axis: normalize 8 values strided by `plane4` float4s.
__global__ void softmax_b8(float4* __restrict__ d, int plane4)
{
    const int i = blockIdx.x * blockDim.x + threadIdx.x;
    if (i >= plane4) return;
    float4 v[B_SZ];
    float4 m = make_float4(-1e30f, -1e30f, -1e30f, -1e30f);
#pragma unroll
    for (int b = 0; b < B_SZ; ++b) {
        v[b] = d[(size_t)b * plane4 + i];
        m.x = fmaxf(m.x, v[b].x); m.y = fmaxf(m.y, v[b].y);
        m.z = fmaxf(m.z, v[b].z); m.w = fmaxf(m.w, v[b].w);
    }
    float4 s = make_float4(0.f, 0.f, 0.f, 0.f);
#pragma unroll
    for (int b = 0; b < B_SZ; ++b) {
        v[b].x = __expf(v[b].x - m.x); s.x += v[b].x;
        v[b].y = __expf(v[b].y - m.y); s.y += v[b].y;
        v[b].z = __expf(v[b].z - m.z); s.z += v[b].z;
        v[b].w = __expf(v[b].w - m.w); s.w += v[b].w;
    }
    s.x = 1.f / s.x; s.y = 1.f / s.y; s.z = 1.f / s.z; s.w = 1.f / s.w;
#pragma unroll
    for (int b = 0; b < B_SZ; ++b) {
        v[b].x *= s.x; v[b].y *= s.y; v[b].z *= s.z; v[b].w *= s.w;
        d[(size_t)b * plane4 + i] = v[b];
    }
}

extern "C" void kernel_launch(void* const* d_in, const int* in_sizes, int n_in,
                              void* d_out, int out_size)
{
    (void)in_sizes; (void)n_in; (void)out_size;
    const float* key   = (const float*)d_in[0];
    const float* value = (const float*)d_in[1];
    const float* query = (const float*)d_in[2];
    const float* Wk = (const float*)d_in[3];
    const float* bk = (const float*)d_in[4];
    const float* Wv = (const float*)d_in[5];
    const float* bv = (const float*)d_in[6];
    const float* Wq = (const float*)d_in[7];
    const float* bq = (const float*)d_in[8];
    const float* Wo = (const float*)d_in[9];
    const float* bo = (const float*)d_in[10];
    float* out = (float*)d_out;

    float *q, *k, *v, *att, *att2;
    cudaGetSymbolAddress((void**)&q, g_q);
    cudaGetSymbolAddress((void**)&k, g_k);
    cudaGetSymbolAddress((void**)&v, g_v);
    cudaGetSymbolAddress((void**)&att, g_att);
    cudaGetSymbolAddress((void**)&att2, g_att2);

    // Allow 147KB dynamic smem (idempotent; not a stream op, capture-safe).
    cudaFuncSetAttribute((const void*)gemm_tf32<true, true>,
                         cudaFuncAttributeMaxDynamicSharedMemorySize, SMEM_BYTES);
    cudaFuncSetAttribute((const void*)gemm_tf32<true, false>,
                         cudaFuncAttributeMaxDynamicSharedMemorySize, SMEM_BYTES);
    cudaFuncSetAttribute((const void*)gemm_tf32<false, false>,
                         cudaFuncAttributeMaxDynamicSharedMemorySize, SMEM_BYTES);

    const int MT = B_SZ * T_SZ;  // 16384
    const dim3 blk(256);

    // projections: [16384,512] @ [4096,512]^T + bias
    {
        dim3 grid(HE_SZ / 128, MT / 128, 1);
        gemm_tf32<true, true><<<grid, blk, SMEM_BYTES>>>(key, Wk, bk, k, MT, HE_SZ, E_SZ, 1.f, 0, 0, 0);
        gemm_tf32<true, true><<<grid, blk, SMEM_BYTES>>>(query, Wq, bq, q, MT, HE_SZ, E_SZ, 1.f, 0, 0, 0);
        gemm_tf32<true, true><<<grid, blk, SMEM_BYTES>>>(value, Wv, bv, v, MT, HE_SZ, E_SZ, 1.f, 0, 0, 0);
    }
    // logits: per batch, [2048,4096] @ [2048,4096]^T * SCALE
    {
        dim3 grid(T_SZ / 128, T_SZ / 128, B_SZ);
        const long long sqk = (long long)T_SZ * HE_SZ;
        const long long sp = (long long)T_SZ * T_SZ;
        gemm_tf32<true, false><<<grid, blk, SMEM_BYTES>>>(q, k, nullptr, att, T_SZ, T_SZ, HE_SZ,
                                                          SCALE_F, sqk, sqk, sp);
    }
    // batch-axis softmax over 8 values
    {
        const int plane4 = (T_SZ * T_SZ) / 4;
        softmax_b8<<<plane4 / 256, 256>>>((float4*)att, plane4);
    }
    // attend: per batch, [2048,2048] @ [2048,4096]
    {
        dim3 grid(HE_SZ / 128, T_SZ / 128, B_SZ);
        const long long sp = (long long)T_SZ * T_SZ;
        const long long sv = (long long)T_SZ * HE_SZ;
        gemm_tf32<false, false><<<grid, blk, SMEM_BYTES>>>(att, v, nullptr, att2, T_SZ, HE_SZ, T_SZ,
                                                           1.f, sp, sv, sv);
    }
    // output projection: [16384,4096] @ [512,4096]^T + bias
    {
        dim3 grid(E_SZ / 128, MT / 128, 1);
        gemm_tf32<true, true><<<grid, blk, SMEM_BYTES>>>(att2, Wo, bo, out, MT, E_SZ, HE_SZ, 1.f, 0, 0, 0);
    }
}